// round 15
// baseline (speedup 1.0000x reference)
#include <cuda_runtime.h>
#include <cub/cub.cuh>

namespace {
constexpr int N_ROWS = 8192;
constexpr int C_COLS = 4096;
constexpr int K_SEL  = 4096;
constexpr int BLOCK  = 512;
constexpr int IPT_L  = 16;            // 512*16 = 8192 elements per column
constexpr int SPT    = K_SEL / BLOCK; // 8 selected slots per thread
constexpr int NBINS  = 2048;          // 11-bit buckets (bits [21,32))
constexpr int NW     = BLOCK / 32;    // 16 warps
constexpr int CPB    = 4;             // columns per block

typedef cub::BlockScan<int, BLOCK>          Scan;
typedef cub::BlockReduce<long long, BLOCK>  Reduce;

struct RankSmem {
    unsigned long long pair[K_SEL];   // 32 KB packed (key<<13 | tiebreak) [+ i in bits 48+]
    unsigned int   hist[NBINS];       // 8 KB histogram -> allocator -> bucket END
    unsigned short start[NBINS];      // 4 KB bucket START
    typename Scan::TempStorage scan;
    unsigned int bcast_prefix;
    int          bcast_rk;
};
union SmemUnion {
    RankSmem                     r;
    typename Reduce::TempStorage reduce;
};
}  // namespace

// Column-major staging of f2ord'd keys (static device scratch; no allocs).
__device__ unsigned int g_pk[(size_t)C_COLS * N_ROWS];
__device__ unsigned int g_tk[(size_t)C_COLS * N_ROWS];

__device__ __forceinline__ unsigned int f2ord(float f) {
    // order-preserving float -> uint (ascending)
    unsigned int u = __float_as_uint(f);
    return (u & 0x80000000u) ? ~u : (u | 0x80000000u);
}

__global__ __launch_bounds__(BLOCK, 2) void rankic_kernel(
    const float* __restrict__ preds,
    const float* __restrict__ targets,
    float* __restrict__ out)
{
    __shared__ __align__(16) SmemUnion smem;

    const int t    = threadIdx.x;
    const int warp = t >> 5;
    const int lane = t & 31;
    const int c0   = blockIdx.x * CPB;
    const unsigned long long M45 = (1ull << 45) - 1ull;

    // ========== Phase 0: float4 loads; coalesced column-major key staging.
#pragma unroll
    for (int e = 0; e < IPT_L; ++e) {
        const int row = e * BLOCK + t;
        const float4 p4 = __ldg(reinterpret_cast<const float4*>(
            &preds[(size_t)row * C_COLS + c0]));
        const float4 t4 = __ldg(reinterpret_cast<const float4*>(
            &targets[(size_t)row * C_COLS + c0]));
        g_pk[(size_t)(c0 + 0) * N_ROWS + row] = f2ord(p4.x);
        g_pk[(size_t)(c0 + 1) * N_ROWS + row] = f2ord(p4.y);
        g_pk[(size_t)(c0 + 2) * N_ROWS + row] = f2ord(p4.z);
        g_pk[(size_t)(c0 + 3) * N_ROWS + row] = f2ord(p4.w);
        g_tk[(size_t)(c0 + 0) * N_ROWS + row] = f2ord(t4.x);
        g_tk[(size_t)(c0 + 1) * N_ROWS + row] = f2ord(t4.y);
        g_tk[(size_t)(c0 + 2) * N_ROWS + row] = f2ord(t4.z);
        g_tk[(size_t)(c0 + 3) * N_ROWS + row] = f2ord(t4.w);
    }
    __syncthreads();

    for (int j = 0; j < CPB; ++j) {
        const int c = c0 + j;

        // ---- Load p-keys (blocked: row = t*IPT_L + e), coalesced uint4.
        unsigned int keys[IPT_L];
#pragma unroll
        for (int e4 = 0; e4 < IPT_L / 4; ++e4) {
            const uint4 kk = *reinterpret_cast<const uint4*>(
                &g_pk[(size_t)c * N_ROWS + t * IPT_L + e4 * 4]);
            keys[e4 * 4 + 0] = kk.x;
            keys[e4 * 4 + 1] = kk.y;
            keys[e4 * 4 + 2] = kk.z;
            keys[e4 * 4 + 3] = kk.w;
        }

        // ---- Radix-select k-th largest (exact; rounds of 11/11/10 bits).
        const int SH[3] = {21, 10, 0};
        const int WD[3] = {11, 11, 10};
        unsigned int prefix = 0;
        int rk = K_SEL;
#pragma unroll
        for (int r = 0; r < 3; ++r) {
            const int sh = SH[r], wd = WD[r];
            const int nb = 1 << wd;
            const unsigned int dmask = (unsigned int)(nb - 1);
            for (int i = t; i < NBINS; i += BLOCK) smem.r.hist[i] = 0;
            __syncthreads();
#pragma unroll
            for (int e = 0; e < IPT_L; ++e) {
                const unsigned int k_ = keys[e];
                const bool match = (r == 0) || ((k_ >> (sh + wd)) == prefix);
                if (match) atomicAdd(&smem.r.hist[(k_ >> sh) & dmask], 1u);
            }
            __syncthreads();
            int val[4], cum[4];
#pragma unroll
            for (int i = 0; i < 4; ++i) {
                int idx = t * 4 + i;
                val[i] = (idx < nb) ? (int)smem.r.hist[nb - 1 - idx] : 0;
            }
            Scan(smem.r.scan).InclusiveSum(val, cum);
#pragma unroll
            for (int i = 0; i < 4; ++i) {
                int idx = t * 4 + i;
                if (idx < nb && cum[i] >= rk && (cum[i] - val[i]) < rk) {
                    smem.r.bcast_prefix = (prefix << wd) | (unsigned int)(nb - 1 - idx);
                    smem.r.bcast_rk     = rk - (cum[i] - val[i]);
                }
            }
            __syncthreads();
            prefix = smem.r.bcast_prefix;
            rk     = smem.r.bcast_rk;
            __syncthreads();
        }
        const unsigned int Kstar = prefix;
        const int rkF = rk;

        // ---- Fused (gt, eq) scan; build exact index-order selection mask.
        int cnt_gt = 0, cnt_eq = 0;
#pragma unroll
        for (int e = 0; e < IPT_L; ++e) {
            cnt_gt += (keys[e] > Kstar);
            cnt_eq += (keys[e] == Kstar);
        }
        int packedBase;
        Scan(smem.r.scan).ExclusiveSum((cnt_gt << 16) | cnt_eq, packedBase);
        const int eqBase = packedBase & 0xFFFF;
        unsigned int selMask = 0;
        {
            int eqs = 0;
#pragma unroll
            for (int e = 0; e < IPT_L; ++e) {
                bool s;
                if (keys[e] > Kstar)        s = true;
                else if (keys[e] == Kstar)  { s = (eqBase + eqs) < rkF; ++eqs; }
                else                         s = false;
                selMask |= (unsigned int)s << e;
            }
        }
        __syncthreads();

        // ---- Histogram selected p-keys by top-11 bits.
        for (int i = t; i < NBINS; i += BLOCK) smem.r.hist[i] = 0;
        __syncthreads();
#pragma unroll
        for (int e = 0; e < IPT_L; ++e)
            if ((selMask >> e) & 1u) atomicAdd(&smem.r.hist[keys[e] >> 21], 1u);
        __syncthreads();

        // ---- Descending exclusive scan -> bucket start + allocator.
        {
            int val[4], cum[4];
#pragma unroll
            for (int i = 0; i < 4; ++i)
                val[i] = (int)smem.r.hist[NBINS - 1 - (t * 4 + i)];
            Scan(smem.r.scan).InclusiveSum(val, cum);
            __syncthreads();   // all hist reads complete before overwrite
#pragma unroll
            for (int i = 0; i < 4; ++i) {
                const int bin  = NBINS - 1 - (t * 4 + i);
                const int excl = cum[i] - val[i];
                smem.r.start[bin] = (unsigned short)excl;
                smem.r.hist[bin]  = (unsigned int)excl;   // becomes allocator
            }
        }
        __syncthreads();

        // ---- Scatter selected pairs: (key<<13) | (8191 - rowIdx).
        //      Descending pair order == (key desc, rowIdx asc) == top_k order.
#pragma unroll
        for (int e = 0; e < IPT_L; ++e) {
            if ((selMask >> e) & 1u) {
                const unsigned int k_ = keys[e];
                const int slot = (int)atomicAdd(&smem.r.hist[k_ >> 21], 1u);
                smem.r.pair[slot] = ((unsigned long long)k_ << 13)
                                  | (unsigned long long)(8191 - (t * IPT_L + e));
            }
        }
        __syncthreads();

        // ---- p-rank (descending, exact): i = start + #(pair_j > own).
        //      Write i into bits [48,61); comparisons mask to 45 bits, so
        //      in-place writeback never perturbs other comparisons.
        for (int d = warp; d < NBINS; d += NW) {
            const int lo = (int)smem.r.start[d];
            const int hi = (int)smem.r.hist[d];
            for (int q = lo; q < hi; ++q) {
                const unsigned long long own = smem.r.pair[q] & M45;
                int cnt = 0;
                for (int jb = lo; jb < hi; jb += 32) {
                    const int ix  = jb + lane;
                    const bool pr = (ix < hi) && ((smem.r.pair[ix] & M45) > own);
                    cnt += __popc(__ballot_sync(0xffffffffu, pr));
                }
                if (lane == (q & 31))
                    smem.r.pair[q] |= (unsigned long long)(lo + cnt) << 48;
            }
        }
        __syncthreads();

        // ---- Read back (rowIdx, i); gather t-key; build t-pairs in regs.
        unsigned long long tp[SPT];
#pragma unroll
        for (int e = 0; e < SPT; ++e) {
            const unsigned long long pr = smem.r.pair[t * SPT + e];
            const int row = 8191 - (int)(pr & 0x1FFFull);
            const unsigned int i_ = (unsigned int)(pr >> 48) & 0x1FFFu;
            const unsigned int tk = g_tk[(size_t)c * N_ROWS + row];
            tp[e] = ((unsigned long long)tk << 13) | (unsigned long long)i_;
        }
        __syncthreads();   // pair[] fully consumed before reuse

        // ---- Histogram t-keys by top-11 bits (pair>>34 = tk>>21).
        for (int i = t; i < NBINS; i += BLOCK) smem.r.hist[i] = 0;
        __syncthreads();
#pragma unroll
        for (int e = 0; e < SPT; ++e)
            atomicAdd(&smem.r.hist[(unsigned int)(tp[e] >> 34)], 1u);
        __syncthreads();

        // ---- Ascending exclusive scan -> start + allocator.
        {
            int val[4], cum[4];
#pragma unroll
            for (int i = 0; i < 4; ++i)
                val[i] = (int)smem.r.hist[t * 4 + i];
            Scan(smem.r.scan).InclusiveSum(val, cum);
            __syncthreads();
#pragma unroll
            for (int i = 0; i < 4; ++i) {
                const int bin  = t * 4 + i;
                const int excl = cum[i] - val[i];
                smem.r.start[bin] = (unsigned short)excl;
                smem.r.hist[bin]  = (unsigned int)excl;
            }
        }
        __syncthreads();

        // ---- Scatter t-pairs.
#pragma unroll
        for (int e = 0; e < SPT; ++e) {
            const int d    = (int)(tp[e] >> 34);
            const int slot = (int)atomicAdd(&smem.r.hist[d], 1u);
            smem.r.pair[slot] = tp[e];
        }
        __syncthreads();

        // ---- t-rank (ascending, exact; ties by i = reference semantics).
        //      r = start + #(pair_j < own); accumulate S += r*i inline.
        long long sloc = 0;
        for (int d = warp; d < NBINS; d += NW) {
            const int lo = (int)smem.r.start[d];
            const int hi = (int)smem.r.hist[d];
            for (int q = lo; q < hi; ++q) {
                const unsigned long long own = smem.r.pair[q];
                int cnt = 0;
                for (int jb = lo; jb < hi; jb += 32) {
                    const int ix  = jb + lane;
                    const bool pr = (ix < hi) && (smem.r.pair[ix] < own);
                    cnt += __popc(__ballot_sync(0xffffffffu, pr));
                }
                if (lane == (q & 31))
                    sloc += (long long)(lo + cnt) * (long long)(own & 0x1FFFull);
            }
        }
        __syncthreads();   // rank phase done before union flips to reduce

        long long S = Reduce(smem.reduce).Sum(sloc);

        if (t == 0) {
            // p_r[i] = k-1-i  =>  sum(p_r*t_r) = (k-1)*k*(k-1)/2 - S
            const double k   = (double)K_SEL;
            double PT    = (k - 1.0) * (k * (k - 1.0) * 0.5) - (double)S;
            double m     = (k - 1.0) * 0.5;
            double cov   = PT / k - m * m;                 // ddof=0 rank covariance
            double denom = k * (k + 1.0) / 12.0 + 1e-8;    // exact ddof=1 std product
            out[c] = (float)(cov / denom);
        }
        __syncthreads();   // reduce storage drained before next column
    }
}

extern "C" void kernel_launch(void* const* d_in, const int* in_sizes, int n_in,
                              void* d_out, int out_size) {
    const float* preds   = (const float*)d_in[0];
    const float* targets = (const float*)d_in[1];
    float*       out     = (float*)d_out;

    (void)in_sizes; (void)n_in; (void)out_size;

    rankic_kernel<<<C_COLS / CPB, BLOCK>>>(preds, targets, out);
}

// round 16
// speedup vs baseline: 13.7323x; 13.7323x over previous
#include <cuda_runtime.h>
#include <cub/cub.cuh>

namespace {
constexpr int N_ROWS = 8192;
constexpr int C_COLS = 4096;
constexpr int K_SEL  = 4096;
constexpr int BLOCK  = 512;
constexpr int IPT_L  = 16;   // per-column elements per thread: 512*16 = 8192
constexpr int IPT_S  = 8;    // sort phase: 512*8 = 4096
constexpr int NBINS  = 2048; // select histogram
constexpr int CPB    = 4;    // columns per block (float4 load amortization)

// Sort only bits [SORT_LO, 32): 25 bits -> 5 radix passes (CUB 5-bit digits).
// Truncation rel_err measured 1.378e-4 (R7..R13), well under 1e-3.
constexpr int SORT_LO = 7;

typedef cub::BlockRadixSort<unsigned int, BLOCK, IPT_S, unsigned short, 5> Sort;
typedef cub::BlockScan<int, BLOCK>          Scan;
typedef cub::BlockReduce<long long, BLOCK>  Reduce;

struct SelectSmem {
    unsigned int hist[NBINS];
    typename Scan::TempStorage scan;
    unsigned int bcast_prefix;
    int          bcast_rk;
};
struct CompactSmem {
    unsigned int   cKey[K_SEL];
    unsigned short cIdx[K_SEL];
};
struct TColSmem {
    unsigned int tCol[N_ROWS];     // 32 KB staged target column (f2ord'd)
};
union SmemUnion {
    typename Sort::TempStorage   sort;
    SelectSmem                   sel;
    CompactSmem                  cmp;
    TColSmem                     tcl;
    typename Reduce::TempStorage reduce;
};
}  // namespace

// Column-major staging scratch (f2ord'd keys); static device arrays (no allocs).
__device__ unsigned int g_pk[(size_t)C_COLS * N_ROWS];
__device__ unsigned int g_tk[(size_t)C_COLS * N_ROWS];

__device__ __forceinline__ unsigned int f2ord(float f) {
    // order-preserving float -> uint (ascending)
    unsigned int u = __float_as_uint(f);
    return (u & 0x80000000u) ? ~u : (u | 0x80000000u);
}

// Cap regs at 64 -> 2 blocks/SM (occ ~49%); validated R8.
__global__ __launch_bounds__(BLOCK, 2) void rankic_kernel(
    const float* __restrict__ preds,
    const float* __restrict__ targets,
    float* __restrict__ out)
{
    __shared__ __align__(16) SmemUnion smem;

    const int t  = threadIdx.x;
    const int c0 = blockIdx.x * CPB;

    // ========== Phase 0: float4 loads of 4 columns of preds AND targets;
    //            coalesced column-major stores of f2ord'd keys to scratch.
#pragma unroll
    for (int e = 0; e < IPT_L; ++e) {
        const int row = e * BLOCK + t;
        const float4 p4 = __ldg(reinterpret_cast<const float4*>(
            &preds[(size_t)row * C_COLS + c0]));
        const float4 t4 = __ldg(reinterpret_cast<const float4*>(
            &targets[(size_t)row * C_COLS + c0]));
        g_pk[(size_t)(c0 + 0) * N_ROWS + row] = f2ord(p4.x);
        g_pk[(size_t)(c0 + 1) * N_ROWS + row] = f2ord(p4.y);
        g_pk[(size_t)(c0 + 2) * N_ROWS + row] = f2ord(p4.z);
        g_pk[(size_t)(c0 + 3) * N_ROWS + row] = f2ord(p4.w);
        g_tk[(size_t)(c0 + 0) * N_ROWS + row] = f2ord(t4.x);
        g_tk[(size_t)(c0 + 1) * N_ROWS + row] = f2ord(t4.y);
        g_tk[(size_t)(c0 + 2) * N_ROWS + row] = f2ord(t4.z);
        g_tk[(size_t)(c0 + 3) * N_ROWS + row] = f2ord(t4.w);
    }
    __syncthreads();

    // ========== Per-column pipeline.
    for (int j = 0; j < CPB; ++j) {
        const int c = c0 + j;

        // ---- Reload p-keys, blocked order (row = t*IPT_L + e), coalesced uint4.
        unsigned int keys[IPT_L];
#pragma unroll
        for (int e4 = 0; e4 < IPT_L / 4; ++e4) {
            const uint4 kk = *reinterpret_cast<const uint4*>(
                &g_pk[(size_t)c * N_ROWS + t * IPT_L + e4 * 4]);
            keys[e4 * 4 + 0] = kk.x;
            keys[e4 * 4 + 1] = kk.y;
            keys[e4 * 4 + 2] = kk.z;
            keys[e4 * 4 + 3] = kk.w;
        }

        // ---- Radix-select to a 22-bit threshold (2 rounds of 11 bits).
        //      Boundary elements equal in their top 22 bits are taken in index
        //      order; their p-values differ by <2^-12 relative -> ic impact
        //      ~1e-5/column, same class as the tolerated sort truncation.
        const int SH[2] = {21, 10};
        unsigned int prefix = 0;
        int rk = K_SEL;
#pragma unroll
        for (int r = 0; r < 2; ++r) {
            const int sh = SH[r];
            for (int i = t; i < NBINS; i += BLOCK) smem.sel.hist[i] = 0;
            __syncthreads();
#pragma unroll
            for (int e = 0; e < IPT_L; ++e) {
                const unsigned int k_ = keys[e];
                const bool match = (r == 0) || ((k_ >> (sh + 11)) == prefix);
                if (match) atomicAdd(&smem.sel.hist[(k_ >> sh) & 2047u], 1u);
            }
            __syncthreads();
            int val[4], cum[4];
#pragma unroll
            for (int i = 0; i < 4; ++i) {
                int idx = t * 4 + i;
                val[i] = (int)smem.sel.hist[NBINS - 1 - idx];
            }
            Scan(smem.sel.scan).InclusiveSum(val, cum);
#pragma unroll
            for (int i = 0; i < 4; ++i) {
                int idx = t * 4 + i;
                if (cum[i] >= rk && (cum[i] - val[i]) < rk) {   // exactly one
                    smem.sel.bcast_prefix = (prefix << 11) | (unsigned int)(NBINS - 1 - idx);
                    smem.sel.bcast_rk     = rk - (cum[i] - val[i]);
                }
            }
            __syncthreads();
            prefix = smem.sel.bcast_prefix;
            rk     = smem.sel.bcast_rk;
            __syncthreads();
        }
        const unsigned int Kstar22 = prefix;   // 22-bit threshold prefix
        const int rkF = rk;                    // #eq-prefix elems to take (index order)

        // ---- Fused (gt, eq) scan + stable index-order compaction (22-bit cmp).
        int cnt_gt = 0, cnt_eq = 0;
#pragma unroll
        for (int e = 0; e < IPT_L; ++e) {
            const unsigned int hp = keys[e] >> 10;
            cnt_gt += (hp > Kstar22);
            cnt_eq += (hp == Kstar22);
        }
        int packedBase;
        Scan(smem.sel.scan).ExclusiveSum((cnt_gt << 16) | cnt_eq, packedBase);
        const int gtBase = packedBase >> 16;
        const int eqBase = packedBase & 0xFFFF;
        __syncthreads();
        {
            int gts = 0, eqs = 0;
#pragma unroll
            for (int e = 0; e < IPT_L; ++e) {
                const unsigned int k_ = keys[e];
                const unsigned int hp = k_ >> 10;
                if (hp > Kstar22) {
                    int slot = gtBase + gts + min(eqBase + eqs, rkF);
                    smem.cmp.cKey[slot] = k_;
                    smem.cmp.cIdx[slot] = (unsigned short)(t * IPT_L + e);
                    ++gts;
                } else if (hp == Kstar22) {
                    int eo = eqBase + eqs;
                    if (eo < rkF) {
                        int slot = gtBase + gts + eo;
                        smem.cmp.cKey[slot] = k_;
                        smem.cmp.cIdx[slot] = (unsigned short)(t * IPT_L + e);
                    }
                    ++eqs;
                }
            }
        }
        __syncthreads();

        // ---- Sort 1: selected preds descending, stable -> pos = topk order i.
        unsigned int   k2[IPT_S];
        unsigned short v2[IPT_S];
#pragma unroll
        for (int e = 0; e < IPT_S; ++e) {
            int pos = t * IPT_S + e;
            k2[e] = smem.cmp.cKey[pos];
            v2[e] = smem.cmp.cIdx[pos];
        }
        __syncthreads();   // compaction arrays consumed; sort storage takes over
        Sort(smem.sort).SortDescending(k2, v2, SORT_LO, 32);
        __syncthreads();   // sort storage dead; tCol staging takes the union

        // ---- Stage the f2ord'd target column into shared, gather via LDS.
        {
            const unsigned int* __restrict__ tc = &g_tk[(size_t)c * N_ROWS];
            for (int i4 = t; i4 < N_ROWS / 4; i4 += BLOCK) {
                const uint4 tv = *reinterpret_cast<const uint4*>(&tc[i4 * 4]);
                *reinterpret_cast<uint4*>(&smem.tcl.tCol[i4 * 4]) = tv;
            }
        }
        __syncthreads();
#pragma unroll
        for (int e = 0; e < IPT_S; ++e) {
            int pos = t * IPT_S + e;   // descending-p rank i
            k2[e] = smem.tcl.tCol[v2[e]];
            v2[e] = (unsigned short)pos;
        }
        __syncthreads();   // tCol consumed; sort storage takes the union again

        // ---- Sort 2: t-keys ascending, stable (ties -> i order), payload = i.
        Sort(smem.sort).Sort(k2, v2, SORT_LO, 32);
        __syncthreads();

        // ---- S = sum over ascending-t rank r of r * i(r), exact in int64.
        long long s = 0;
#pragma unroll
        for (int e = 0; e < IPT_S; ++e)
            s += (long long)(t * IPT_S + e) * (long long)v2[e];
        long long S = Reduce(smem.reduce).Sum(s);

        if (t == 0) {
            // p_r[i] = k-1-i  =>  sum(p_r*t_r) = (k-1)*k*(k-1)/2 - S
            const double k   = (double)K_SEL;
            double PT    = (k - 1.0) * (k * (k - 1.0) * 0.5) - (double)S;
            double m     = (k - 1.0) * 0.5;
            double cov   = PT / k - m * m;
            double denom = k * (k + 1.0) / 12.0 + 1e-8;
            out[c] = (float)(cov / denom);
        }
        __syncthreads();   // reduce storage drained before next column's select
    }
}

extern "C" void kernel_launch(void* const* d_in, const int* in_sizes, int n_in,
                              void* d_out, int out_size) {
    const float* preds   = (const float*)d_in[0];
    const float* targets = (const float*)d_in[1];
    float*       out     = (float*)d_out;

    (void)in_sizes; (void)n_in; (void)out_size;

    rankic_kernel<<<C_COLS / CPB, BLOCK>>>(preds, targets, out);
}

// round 17
// speedup vs baseline: 15.2019x; 1.1070x over previous
#include <cuda_runtime.h>
#include <cub/cub.cuh>

namespace {
constexpr int N_ROWS = 8192;
constexpr int C_COLS = 4096;
constexpr int K_SEL  = 4096;
constexpr int BLOCK  = 512;
constexpr int IPT_L  = 16;            // 512*16 = 8192 elements per column
constexpr int SPT    = K_SEL / BLOCK; // 8 slots per thread in rank phases
constexpr int NBINS  = 2048;          // value bins (top-11 key bits) AND rank bins
constexpr int CPB    = 4;             // columns per block

typedef cub::BlockScan<int, BLOCK>          Scan;
typedef cub::BlockReduce<long long, BLOCK>  Reduce;

struct Smem {
    unsigned int   pairHi[K_SEL];   // 16 KB full 32-bit keys
    unsigned short pairLo[K_SEL];   // 8 KB  13-bit tie (p: 8191-idx asc->desc; t: i)
    unsigned int   hist[NBINS];     // 8 KB  (select hist / value hist / rank allocator)
    unsigned int   basecnt[NBINS];  // 8 KB  per value-bin: (rankBase<<16)|cnt
    union {
        typename Scan::TempStorage   scan;
        typename Reduce::TempStorage red;
    } tmp;
    unsigned int bcast_prefix;
    int          bcast_rk;
};
}  // namespace

// Column-major staging of f2ord'd keys (static device scratch; no allocs).
__device__ unsigned int g_pk[(size_t)C_COLS * N_ROWS];
__device__ unsigned int g_tk[(size_t)C_COLS * N_ROWS];

__device__ __forceinline__ unsigned int f2ord(float f) {
    // order-preserving float -> uint (ascending)
    unsigned int u = __float_as_uint(f);
    return (u & 0x80000000u) ? ~u : (u | 0x80000000u);
}

// Monotone data-adaptive rank-bin map. basecnt[b] = (rankBase<<16)|cnt for
// value-bin b = key>>21 (rankBase in desired rank order). frac = next 10 bits.
// DESC=true: rank space descends with key. Pure integer ops -> exactly monotone:
// pair1 beats pair2  =>  rb1 <= rb2.
template <bool DESC>
__device__ __forceinline__ unsigned int rank_bin(
    unsigned int key, const unsigned int* __restrict__ basecnt)
{
    const unsigned int bc   = basecnt[key >> 21];
    const unsigned int base = bc >> 16;
    const unsigned int cnt  = bc & 0xFFFFu;
    const unsigned int frac = (key >> 11) & 1023u;
    const unsigned int est  = (cnt * (DESC ? (1023u - frac) : frac)) >> 10;  // <= cnt-1
    return (base + est) >> 1;   // 4096 rank positions -> 2048 rank bins
}

__global__ __launch_bounds__(BLOCK, 2) void rankic_kernel(
    const float* __restrict__ preds,
    const float* __restrict__ targets,
    float* __restrict__ out)
{
    __shared__ __align__(16) Smem smem;

    const int t  = threadIdx.x;
    const int c0 = blockIdx.x * CPB;

    // ========== Phase 0: float4 loads; coalesced column-major key staging.
#pragma unroll
    for (int e = 0; e < IPT_L; ++e) {
        const int row = e * BLOCK + t;
        const float4 p4 = __ldg(reinterpret_cast<const float4*>(
            &preds[(size_t)row * C_COLS + c0]));
        const float4 t4 = __ldg(reinterpret_cast<const float4*>(
            &targets[(size_t)row * C_COLS + c0]));
        g_pk[(size_t)(c0 + 0) * N_ROWS + row] = f2ord(p4.x);
        g_pk[(size_t)(c0 + 1) * N_ROWS + row] = f2ord(p4.y);
        g_pk[(size_t)(c0 + 2) * N_ROWS + row] = f2ord(p4.z);
        g_pk[(size_t)(c0 + 3) * N_ROWS + row] = f2ord(p4.w);
        g_tk[(size_t)(c0 + 0) * N_ROWS + row] = f2ord(t4.x);
        g_tk[(size_t)(c0 + 1) * N_ROWS + row] = f2ord(t4.y);
        g_tk[(size_t)(c0 + 2) * N_ROWS + row] = f2ord(t4.z);
        g_tk[(size_t)(c0 + 3) * N_ROWS + row] = f2ord(t4.w);
    }
    __syncthreads();

    for (int j = 0; j < CPB; ++j) {
        const int c = c0 + j;

        // ---- Load p-keys (blocked: row = t*IPT_L + e), coalesced uint4.
        unsigned int keys[IPT_L];
#pragma unroll
        for (int e4 = 0; e4 < IPT_L / 4; ++e4) {
            const uint4 kk = *reinterpret_cast<const uint4*>(
                &g_pk[(size_t)c * N_ROWS + t * IPT_L + e4 * 4]);
            keys[e4 * 4 + 0] = kk.x;
            keys[e4 * 4 + 1] = kk.y;
            keys[e4 * 4 + 2] = kk.z;
            keys[e4 * 4 + 3] = kk.w;
        }

        // ---- Radix-select to 22-bit threshold (2 x 11-bit rounds; R16-validated).
        const int SH[2] = {21, 10};
        unsigned int prefix = 0;
        int rk = K_SEL;
#pragma unroll
        for (int r = 0; r < 2; ++r) {
            const int sh = SH[r];
            for (int i = t; i < NBINS; i += BLOCK) smem.hist[i] = 0;
            __syncthreads();
#pragma unroll
            for (int e = 0; e < IPT_L; ++e) {
                const unsigned int k_ = keys[e];
                const bool match = (r == 0) || ((k_ >> (sh + 11)) == prefix);
                if (match) atomicAdd(&smem.hist[(k_ >> sh) & 2047u], 1u);
            }
            __syncthreads();
            int val[4], cum[4];
#pragma unroll
            for (int i = 0; i < 4; ++i)
                val[i] = (int)smem.hist[NBINS - 1 - (t * 4 + i)];
            Scan(smem.tmp.scan).InclusiveSum(val, cum);
#pragma unroll
            for (int i = 0; i < 4; ++i) {
                const int idx = t * 4 + i;
                if (cum[i] >= rk && (cum[i] - val[i]) < rk) {   // exactly one
                    smem.bcast_prefix = (prefix << 11) | (unsigned int)(NBINS - 1 - idx);
                    smem.bcast_rk     = rk - (cum[i] - val[i]);
                }
            }
            __syncthreads();
            prefix = smem.bcast_prefix;
            rk     = smem.bcast_rk;
            __syncthreads();
        }
        const unsigned int Kstar22 = prefix;
        const int rkF = rk;

        // ---- (gt, eq) scan in index order -> selection mask (22-bit compare).
        int cnt_gt = 0, cnt_eq = 0;
#pragma unroll
        for (int e = 0; e < IPT_L; ++e) {
            const unsigned int hp = keys[e] >> 10;
            cnt_gt += (hp > Kstar22);
            cnt_eq += (hp == Kstar22);
        }
        int packedBase;
        Scan(smem.tmp.scan).ExclusiveSum((cnt_gt << 16) | cnt_eq, packedBase);
        const int eqBase = packedBase & 0xFFFF;
        unsigned int selMask = 0;
        {
            int eqs = 0;
#pragma unroll
            for (int e = 0; e < IPT_L; ++e) {
                const unsigned int hp = keys[e] >> 10;
                bool s;
                if (hp > Kstar22)       s = true;
                else if (hp == Kstar22) { s = (eqBase + eqs) < rkF; ++eqs; }
                else                     s = false;
                selMask |= (unsigned int)s << e;
            }
        }
        __syncthreads();

        // ================== P-SIDE: exact descending ranks ==================
        // 1) value histogram of selected p-keys (top-11 bits).
        for (int i = t; i < NBINS; i += BLOCK) smem.hist[i] = 0;
        __syncthreads();
#pragma unroll
        for (int e = 0; e < IPT_L; ++e)
            if ((selMask >> e) & 1u) atomicAdd(&smem.hist[keys[e] >> 21], 1u);
        __syncthreads();
        // 2) DESCENDING exclusive scan -> basecnt[b] = (base<<16)|cnt.
        {
            int val[4], cum[4];
#pragma unroll
            for (int i = 0; i < 4; ++i)
                val[i] = (int)smem.hist[NBINS - 1 - (t * 4 + i)];
            Scan(smem.tmp.scan).InclusiveSum(val, cum);
            __syncthreads();
#pragma unroll
            for (int i = 0; i < 4; ++i) {
                const int bin = NBINS - 1 - (t * 4 + i);
                smem.basecnt[bin] = ((unsigned int)(cum[i] - val[i]) << 16)
                                  | (unsigned int)val[i];
            }
        }
        __syncthreads();
        // 3) rank-bin histogram.
        for (int i = t; i < NBINS; i += BLOCK) smem.hist[i] = 0;
        __syncthreads();
#pragma unroll
        for (int e = 0; e < IPT_L; ++e)
            if ((selMask >> e) & 1u)
                atomicAdd(&smem.hist[rank_bin<true>(keys[e], smem.basecnt)], 1u);
        __syncthreads();
        // 4) ascending scan -> allocator bases (write-back).
        {
            int val[4], cum[4];
#pragma unroll
            for (int i = 0; i < 4; ++i)
                val[i] = (int)smem.hist[t * 4 + i];
            Scan(smem.tmp.scan).InclusiveSum(val, cum);
            __syncthreads();
#pragma unroll
            for (int i = 0; i < 4; ++i)
                smem.hist[t * 4 + i] = (unsigned int)(cum[i] - val[i]);
        }
        __syncthreads();
        // 5) scatter (key, 8191-idx): slot order irrelevant (ranks value-based).
#pragma unroll
        for (int e = 0; e < IPT_L; ++e) {
            if ((selMask >> e) & 1u) {
                const unsigned int k_ = keys[e];
                const unsigned int rb = rank_bin<true>(k_, smem.basecnt);
                const int slot = (int)atomicAdd(&smem.hist[rb], 1u);
                smem.pairHi[slot] = k_;
                smem.pairLo[slot] = (unsigned short)(8191 - (t * IPT_L + e));
            }
        }
        __syncthreads();
        // 6) exact rank i per slot; gather t-key; hold (tkey, i) in registers.
        //    hist[rb] now holds bin END; start = hist[rb-1] (contiguity).
        unsigned int   tkeyR[SPT];
        unsigned short ivR[SPT];
#pragma unroll
        for (int e = 0; e < SPT; ++e) {
            const int s = t * SPT + e;
            const unsigned int  hKey = smem.pairHi[s];
            const unsigned short hTie = smem.pairLo[s];
            const unsigned int rb = rank_bin<true>(hKey, smem.basecnt);
            const int lo = (rb == 0) ? 0 : (int)smem.hist[rb - 1];
            const int hi = (int)smem.hist[rb];
            int cnt = 0;
            for (int q = lo; q < hi; ++q) {
                const unsigned int qk = smem.pairHi[q];
                cnt += (qk > hKey) || (qk == hKey && smem.pairLo[q] > hTie);
            }
            const int i_ = lo + cnt;                 // descending-p rank
            const int row = 8191 - (int)hTie;
            tkeyR[e] = __ldg(&g_tk[(size_t)c * N_ROWS + row]);
            ivR[e]   = (unsigned short)i_;
        }
        __syncthreads();   // p-phase arrays fully consumed

        // ================== T-SIDE: exact ascending ranks ==================
        for (int i = t; i < NBINS; i += BLOCK) smem.hist[i] = 0;
        __syncthreads();
#pragma unroll
        for (int e = 0; e < SPT; ++e)
            atomicAdd(&smem.hist[tkeyR[e] >> 21], 1u);
        __syncthreads();
        {   // ASCENDING scan -> basecnt.
            int val[4], cum[4];
#pragma unroll
            for (int i = 0; i < 4; ++i)
                val[i] = (int)smem.hist[t * 4 + i];
            Scan(smem.tmp.scan).InclusiveSum(val, cum);
            __syncthreads();
#pragma unroll
            for (int i = 0; i < 4; ++i)
                smem.basecnt[t * 4 + i] = ((unsigned int)(cum[i] - val[i]) << 16)
                                        | (unsigned int)val[i];
        }
        __syncthreads();
        for (int i = t; i < NBINS; i += BLOCK) smem.hist[i] = 0;
        __syncthreads();
#pragma unroll
        for (int e = 0; e < SPT; ++e)
            atomicAdd(&smem.hist[rank_bin<false>(tkeyR[e], smem.basecnt)], 1u);
        __syncthreads();
        {   // ascending scan -> allocator bases.
            int val[4], cum[4];
#pragma unroll
            for (int i = 0; i < 4; ++i)
                val[i] = (int)smem.hist[t * 4 + i];
            Scan(smem.tmp.scan).InclusiveSum(val, cum);
            __syncthreads();
#pragma unroll
            for (int i = 0; i < 4; ++i)
                smem.hist[t * 4 + i] = (unsigned int)(cum[i] - val[i]);
        }
        __syncthreads();
#pragma unroll
        for (int e = 0; e < SPT; ++e) {
            const unsigned int rb = rank_bin<false>(tkeyR[e], smem.basecnt);
            const int slot = (int)atomicAdd(&smem.hist[rb], 1u);
            smem.pairHi[slot] = tkeyR[e];
            smem.pairLo[slot] = ivR[e];            // tie/payload = i (ascending)
        }
        __syncthreads();
        // rank r per slot (ascending; t-ties by i asc = reference); S += r*i.
        long long sloc = 0;
#pragma unroll
        for (int e = 0; e < SPT; ++e) {
            const int s = t * SPT + e;
            const unsigned int  hKey = smem.pairHi[s];
            const unsigned short hTie = smem.pairLo[s];
            const unsigned int rb = rank_bin<false>(hKey, smem.basecnt);
            const int lo = (rb == 0) ? 0 : (int)smem.hist[rb - 1];
            const int hi = (int)smem.hist[rb];
            int cnt = 0;
            for (int q = lo; q < hi; ++q) {
                const unsigned int qk = smem.pairHi[q];
                cnt += (qk < hKey) || (qk == hKey && smem.pairLo[q] < hTie);
            }
            sloc += (long long)(lo + cnt) * (long long)hTie;
        }
        __syncthreads();   // rank arrays done before union flips to reduce

        long long S = Reduce(smem.tmp.red).Sum(sloc);

        if (t == 0) {
            // p_r[i] = k-1-i  =>  sum(p_r*t_r) = (k-1)*k*(k-1)/2 - S
            const double k   = (double)K_SEL;
            double PT    = (k - 1.0) * (k * (k - 1.0) * 0.5) - (double)S;
            double m     = (k - 1.0) * 0.5;
            double cov   = PT / k - m * m;                 // ddof=0 rank covariance
            double denom = k * (k + 1.0) / 12.0 + 1e-8;    // exact ddof=1 std product
            out[c] = (float)(cov / denom);
        }
        __syncthreads();   // reduce storage drained before next column
    }
}

extern "C" void kernel_launch(void* const* d_in, const int* in_sizes, int n_in,
                              void* d_out, int out_size) {
    const float* preds   = (const float*)d_in[0];
    const float* targets = (const float*)d_in[1];
    float*       out     = (float*)d_out;

    (void)in_sizes; (void)n_in; (void)out_size;

    rankic_kernel<<<C_COLS / CPB, BLOCK>>>(preds, targets, out);
}